// round 16
// baseline (speedup 1.0000x reference)
#include <cuda_runtime.h>
#include <cuda_fp16.h>
#include <cstdint>
#include <cstddef>

#define Bn 16
#define Tn 2048
#define Dn 1024
#define Hn 512
#define Mn (Bn*Tn)      // 32768
#define Nn 3072
#define Kn 1024

// scratch (static __device__ arrays: allocation-free)
__device__ __half g_Wt[(size_t)Nn * Kn];  // [n'][k], n' = plane*1024 + z*512 + h  (fp16)
__device__ __half g_xh[(size_t)Mn * Kn];  // x in fp16
__device__ __half g_Uh[(size_t)Mn * Nn];  // U in fp16: [m][n'], m = b*T + t

// ------------------------------- helpers -------------------------------
__device__ __forceinline__ uint32_t smem_u32(const void* p) {
    uint32_t a;
    asm("{ .reg .u64 t; cvta.to.shared.u64 t, %1; cvt.u32.u64 %0, t; }" : "=r"(a) : "l"(p));
    return a;
}

#define SWZ(o) ((o) ^ (((o) >> 3) & 0x70))

__device__ __forceinline__ void cp_async16(uint32_t saddr, const void* gptr) {
    asm volatile("cp.async.cg.shared.global [%0], [%1], 16;" :: "r"(saddr), "l"(gptr) : "memory");
}
__device__ __forceinline__ void cp_commit() {
    asm volatile("cp.async.commit_group;" ::: "memory");
}
template<int N> __device__ __forceinline__ void cp_wait() {
    asm volatile("cp.async.wait_group %0;" :: "n"(N) : "memory");
}

#define LDSM4(r, addr) \
    asm volatile("ldmatrix.sync.aligned.m8n8.x4.shared.b16 {%0,%1,%2,%3}, [%4];" \
        : "=r"((r)[0]), "=r"((r)[1]), "=r"((r)[2]), "=r"((r)[3]) : "r"(addr))

#define MMA_F16(d, a, b) \
    asm volatile("mma.sync.aligned.m16n8k16.row.col.f32.f16.f16.f32 " \
        "{%0,%1,%2,%3}, {%4,%5,%6,%7}, {%8,%9}, {%0,%1,%2,%3};" \
        : "+f"((d)[0]), "+f"((d)[1]), "+f"((d)[2]), "+f"((d)[3]) \
        : "r"((a)[0]), "r"((a)[1]), "r"((a)[2]), "r"((a)[3]), "r"((b)[0]), "r"((b)[1]))

// ------------------------- Kernel 0a: x -> fp16 -------------------------
__global__ void __launch_bounds__(256) sru_xh(const float* __restrict__ x) {
    size_t i = (size_t)blockIdx.x * 256 + threadIdx.x;
    float4 v = ((const float4*)x)[i];
    __half2* o = (__half2*)g_xh + i * 2;
    o[0] = __floats2half2_rn(v.x, v.y);
    o[1] = __floats2half2_rn(v.z, v.w);
}

// ------------------------- Kernel 0b: W repack (tiled transpose, fp16) -------------------------
__global__ void __launch_bounds__(256) sru_wt(const float* __restrict__ W) {
    __shared__ float tile[32][33];
    const int tx = threadIdx.x, ty = threadIdx.y;   // 32 x 8
    const int zh0 = blockIdx.x * 32;
    const int d0  = blockIdx.y * 32;
    const int kk  = blockIdx.z;
    #pragma unroll
    for (int r = 0; r < 4; r++) {
        int d = d0 + ty + r * 8;
        int zh = zh0 + tx;
        tile[ty + r * 8][tx] = W[(size_t)d * 3072 + zh * 3 + kk];
    }
    __syncthreads();
    #pragma unroll
    for (int r = 0; r < 4; r++) {
        int zh = zh0 + ty + r * 8;
        int d  = d0 + tx;
        g_Wt[(size_t)(kk * 1024 + zh) * 1024 + d] = __float2half_rn(tile[tx][ty + r * 8]);
    }
}

// ------------------------- Kernel 1: fp16 mma.sync GEMM, 128x128 tiles, 2 CTAs/SM, 1 barrier/chunk -------------------------
#define BM 128
#define BN 128
#define BK 64
#define NCHUNK (Kn / BK)            // 16
#define ASZ (BM * 128)              // 16384 bytes
#define BSZ (BN * 128)              // 16384 bytes
#define STGB (ASZ + BSZ)            // 32768
#define STAGES 3
#define SMEM_TOTAL (STAGES * STGB)  // 98304

__global__ void __launch_bounds__(256, 2) sru_gemm() {
    extern __shared__ __align__(1024) char smem[];
    const uint32_t sb = smem_u32(smem);
    const int tid = threadIdx.x;
    const int lane = tid & 31;
    const int w = tid >> 5;                 // 0..7
    const int m0 = blockIdx.y * BM;
    const int n0 = blockIdx.x * BN;
    const int wm = (w & 3) * 32;            // 4 m-warps
    const int wn = (w >> 2) * 64;           // 2 n-warps

    const int rr  = tid >> 3;   // 0..31
    const int seg = tid & 7;    // 0..7
    const __half* aS = g_xh + (size_t)(m0 + rr) * Kn + seg * 8;
    const __half* bS = g_Wt + (size_t)(n0 + rr) * Kn + seg * 8;
    uint32_t aO[4], bO[4];
    #pragma unroll
    for (int j = 0; j < 4; j++) {
        uint32_t o = (uint32_t)(rr + 32 * j) * 128 + seg * 16;
        aO[j] = SWZ(o);
        bO[j] = ASZ + SWZ(o);
    }

    auto ldchunk = [&](int c, int s) {
        uint32_t st = sb + (uint32_t)s * STGB;
        const __half* ap = aS + c * BK;
        const __half* bp = bS + c * BK;
        #pragma unroll
        for (int j = 0; j < 4; j++) cp_async16(st + aO[j], ap + (size_t)(32 * j) * Kn);
        #pragma unroll
        for (int j = 0; j < 4; j++) cp_async16(st + bO[j], bp + (size_t)(32 * j) * Kn);
        cp_commit();
    };

    uint32_t aRow[2], aXor[2];
    #pragma unroll
    for (int mi = 0; mi < 2; mi++) {
        uint32_t r = wm + mi * 16 + ((lane & 8) ? 8 : 0) + (lane & 7);
        aRow[mi] = r * 128; aXor[mi] = (r & 7) << 4;
    }
    const uint32_t aHi = (lane & 16) ? 16 : 0;
    uint32_t bRow[4], bXor[4];
    #pragma unroll
    for (int p = 0; p < 4; p++) {
        uint32_t r = wn + p * 16 + ((lane & 16) ? 8 : 0) + (lane & 7);
        bRow[p] = ASZ + r * 128; bXor[p] = (r & 7) << 4;
    }
    const uint32_t bHi = (lane & 8) ? 16 : 0;

    float acc[2][8][4];
    #pragma unroll
    for (int mi = 0; mi < 2; mi++)
        #pragma unroll
        for (int nj = 0; nj < 8; nj++)
            #pragma unroll
            for (int q = 0; q < 4; q++) acc[mi][nj][q] = 0.f;

    ldchunk(0, 0);
    ldchunk(1, 1);

    for (int i = 0; i < NCHUNK; i++) {
        if (i < NCHUNK - 1) cp_wait<1>();
        else                cp_wait<0>();
        __syncthreads();
        if (i + 2 < NCHUNK) ldchunk(i + 2, (i + 2) % 3);

        uint32_t st = sb + (uint32_t)(i % 3) * STGB;
        #pragma unroll
        for (int ks = 0; ks < 4; ks++) {
            uint32_t koff = ks * 32;
            uint32_t ar[2][4], br[4][4];
            #pragma unroll
            for (int mi = 0; mi < 2; mi++)
                LDSM4(ar[mi], st + aRow[mi] + ((koff + aHi) ^ aXor[mi]));
            #pragma unroll
            for (int p = 0; p < 4; p++)
                LDSM4(br[p], st + bRow[p] + ((koff + bHi) ^ bXor[p]));
            #pragma unroll
            for (int mi = 0; mi < 2; mi++)
                #pragma unroll
                for (int nj = 0; nj < 8; nj++)
                    MMA_F16(acc[mi][nj], ar[mi], &br[nj >> 1][(nj & 1) * 2]);
        }
    }

    // fp16 epilogue
    const int rowb = m0 + wm + (lane >> 2);
    const int colb = n0 + wn + (lane & 3) * 2;
    #pragma unroll
    for (int mi = 0; mi < 2; mi++)
        #pragma unroll
        for (int nj = 0; nj < 8; nj++) {
            size_t base = (size_t)(rowb + mi * 16) * Nn + colb + nj * 8;
            *(__half2*)(g_Uh + base) = __floats2half2_rn(acc[mi][nj][0], acc[mi][nj][1]);
            *(__half2*)(g_Uh + base + 8 * (size_t)Nn) = __floats2half2_rn(acc[mi][nj][2], acc[mi][nj][3]);
        }
}

// ------------------------- Kernel 2: SRU scan, double-buffered, 1 barrier/tile -------------------------
// 256 blocks x 512 threads; block = (b, z, 64 channels); warp w owns channels 4w..4w+3.
// Lane l covers scan positions 2l, 2l+1 per 64-step tile. Dynamic smem:
//   sbuf[2][3][64][66] halfs (50688 B) + obuf[2][64][65] floats (33280 B) = 83968 B.
#define NT64 (Tn / 64)    // 32 tiles
#define SCAN_SMEM (2*3*64*66*2 + 2*64*65*4)

__global__ void __launch_bounds__(512, 2) sru_scan(const float* __restrict__ bias,
                                                   float* __restrict__ out) {
    extern __shared__ __align__(16) char ssm[];
    __half* sb_ = (__half*)ssm;                  // [2][3][64][66]
    float*  ob_ = (float*)(ssm + 2*3*64*66*2);   // [2][64][65]

    const int tid = threadIdx.x;
    const int lane = tid & 31;
    const int w = tid >> 5;             // 0..15
    const int bx = blockIdx.x;          // 256 blocks: hg(8) z(2) b(16)
    const int hg = bx & 7;
    const int z  = (bx >> 3) & 1;
    const int b  = bx >> 4;
    const int h0 = hg * 64;
    const int fwd = (z == 0);
    const int c0 = 4 * w;

    float bf[4], br[4];
    #pragma unroll
    for (int c = 0; c < 4; c++) {
        bf[c] = bias[z * 1024 + h0 + c0 + c];
        br[c] = bias[z * 1024 + 512 + h0 + c0 + c];
    }

    const size_t bT = (size_t)b * Tn;
    const int tL = tid >> 3, sgL = tid & 7;     // loader role: row tL, 8-half seg sgL

    uint4 ru[3], rx;
    auto load_tile = [&](int it) {
        long t0 = fwd ? (long)it * 64 : (long)(NT64 - 1 - it) * 64;
        #pragma unroll
        for (int p = 0; p < 3; p++)
            ru[p] = *(const uint4*)(g_Uh + (bT + t0 + tL) * Nn + (size_t)p * 1024 + z * 512 + h0 + sgL * 8);
        rx = *(const uint4*)(g_xh + (bT + t0 + tL) * Kn + z * 512 + h0 + sgL * 8);
    };
    auto stage = [&](int buf) {
        #pragma unroll
        for (int p = 0; p < 3; p++) {
            uint32_t* d = (uint32_t*)(sb_ + ((buf * 3 + p) * 64 + tL) * 66 + sgL * 8);
            d[0] = ru[p].x; d[1] = ru[p].y; d[2] = ru[p].z; d[3] = ru[p].w;
        }
    };
    __half* xb_ = sb_ + 2 * 3 * 64 * 66;    // reuse? no -- xbuf needs its own space
    (void)xb_;

    float carry[4] = {0.f, 0.f, 0.f, 0.f};
    const int row0 = fwd ? 2 * lane     : 63 - 2 * lane;
    const int row1 = fwd ? 2 * lane + 1 : 62 - 2 * lane;

    // x residual kept in registers per loader, broadcast through obuf? No -- x is read
    // per (row,channel) by compute. Stage x into plane slot by packing: we fold x into
    // sbuf as a 4th plane is too big; instead reuse: compute reads x from gmem staging
    // in sbuf -- simplest correct: pack x into the unused half of obuf[buf] BEFORE h
    // overwrites it? Hazard. Keep a separate small xsmem double buffer in registers-
    // staged smem: we add it to the dynamic allocation below obuf.
    __half* xs_ = (__half*)(ssm + 2*3*64*66*2 + 2*64*65*4);  // [2][64][66] halfs (+16896 B)

    auto stage_x = [&](int buf) {
        uint32_t* d = (uint32_t*)(xs_ + (buf * 64 + tL) * 66 + sgL * 8);
        d[0] = rx.x; d[1] = rx.y; d[2] = rx.z; d[3] = rx.w;
    };

    // prologue
    load_tile(0);
    stage(0); stage_x(0);
    __syncthreads();
    load_tile(1);

    for (int it = 0; it < NT64; it++) {
        const int buf = it & 1;
        const __half* sg = sb_ + ((buf * 3 + 0) * 64) * 66;
        const __half* sf = sb_ + ((buf * 3 + 1) * 64) * 66;
        const __half* sr = sb_ + ((buf * 3 + 2) * 64) * 66;
        const __half* sx = xs_ + (buf * 64) * 66;

        // read 2 timesteps x 4 channels
        float2 Ga01 = __half22float2(*(const __half2*)(sg + row0 * 66 + c0));
        float2 Ga23 = __half22float2(*(const __half2*)(sg + row0 * 66 + c0 + 2));
        float2 Fa01 = __half22float2(*(const __half2*)(sf + row0 * 66 + c0));
        float2 Fa23 = __half22float2(*(const __half2*)(sf + row0 * 66 + c0 + 2));
        float2 Ra01 = __half22float2(*(const __half2*)(sr + row0 * 66 + c0));
        float2 Ra23 = __half22float2(*(const __half2*)(sr + row0 * 66 + c0 + 2));
        float2 Xa01 = __half22float2(*(const __half2*)(sx + row0 * 66 + c0));
        float2 Xa23 = __half22float2(*(const __half2*)(sx + row0 * 66 + c0 + 2));
        float2 Gb01 = __half22float2(*(const __half2*)(sg + row1 * 66 + c0));
        float2 Gb23 = __half22float2(*(const __half2*)(sg + row1 * 66 + c0 + 2));
        float2 Fb01 = __half22float2(*(const __half2*)(sf + row1 * 66 + c0));
        float2 Fb23 = __half22float2(*(const __half2*)(sf + row1 * 66 + c0 + 2));
        float2 Rb01 = __half22float2(*(const __half2*)(sr + row1 * 66 + c0));
        float2 Rb23 = __half22float2(*(const __half2*)(sr + row1 * 66 + c0 + 2));
        float2 Xb01 = __half22float2(*(const __half2*)(sx + row1 * 66 + c0));
        float2 Xb23 = __half22float2(*(const __half2*)(sx + row1 * 66 + c0 + 2));

        float Ga[4] = {Ga01.x, Ga01.y, Ga23.x, Ga23.y};
        float Fa[4] = {Fa01.x, Fa01.y, Fa23.x, Fa23.y};
        float Ra[4] = {Ra01.x, Ra01.y, Ra23.x, Ra23.y};
        float Xa[4] = {Xa01.x, Xa01.y, Xa23.x, Xa23.y};
        float Gb[4] = {Gb01.x, Gb01.y, Gb23.x, Gb23.y};
        float Fb[4] = {Fb01.x, Fb01.y, Fb23.x, Fb23.y};
        float Rb[4] = {Rb01.x, Rb01.y, Rb23.x, Rb23.y};
        float Xb[4] = {Xb01.x, Xb01.y, Xb23.x, Xb23.y};

        float aa[4], ab[4], ba[4], bb[4], A[4], Bv[4];
        #pragma unroll
        for (int c = 0; c < 4; c++) {
            aa[c] = __fdividef(1.f, 1.f + __expf(-(Fa[c] + bf[c])));
            ab[c] = __fdividef(1.f, 1.f + __expf(-(Fb[c] + bf[c])));
            ba[c] = (1.f - aa[c]) * Ga[c];
            bb[c] = (1.f - ab[c]) * Gb[c];
            A[c]  = ab[c] * aa[c];
            Bv[c] = fmaf(ab[c], ba[c], bb[c]);
        }

        #pragma unroll
        for (int d = 1; d < 32; d <<= 1) {
            float Ap[4], Bp[4];
            #pragma unroll
            for (int c = 0; c < 4; c++) {
                Ap[c] = __shfl_up_sync(0xFFFFFFFFu, A[c], d);
                Bp[c] = __shfl_up_sync(0xFFFFFFFFu, Bv[c], d);
            }
            if (lane >= d) {
                #pragma unroll
                for (int c = 0; c < 4; c++) {
                    Bv[c] = fmaf(A[c], Bp[c], Bv[c]);
                    A[c] *= Ap[c];
                }
            }
        }

        float ca[4], cb[4];
        #pragma unroll
        for (int c = 0; c < 4; c++) {
            float Ae = __shfl_up_sync(0xFFFFFFFFu, A[c], 1);
            float Be = __shfl_up_sync(0xFFFFFFFFu, Bv[c], 1);
            if (lane == 0) { Ae = 1.f; Be = 0.f; }
            float cin = fmaf(Ae, carry[c], Be);
            ca[c] = fmaf(aa[c], cin, ba[c]);
            cb[c] = fmaf(ab[c], ca[c], bb[c]);
            float At = __shfl_sync(0xFFFFFFFFu, A[c], 31);
            float Bt = __shfl_sync(0xFFFFFFFFu, Bv[c], 31);
            carry[c] = fmaf(At, carry[c], Bt);
        }

        float* ob = ob_ + buf * 64 * 65;
        #pragma unroll
        for (int c = 0; c < 4; c++) {
            float rva = __fdividef(1.f, 1.f + __expf(-(Ra[c] + br[c])));
            float rvb = __fdividef(1.f, 1.f + __expf(-(Rb[c] + br[c])));
            float tha = 1.f - 2.f * __fdividef(1.f, 1.f + __expf(2.f * ca[c]));
            float thb = 1.f - 2.f * __fdividef(1.f, 1.f + __expf(2.f * cb[c]));
            ob[row0 * 65 + c0 + c] = fmaf(rva, tha - Xa[c], Xa[c]);
            ob[row1 * 65 + c0 + c] = fmaf(rvb, thb - Xb[c], Xb[c]);
        }

        // stage next tile (other buffer) from prefetched regs, BEFORE the single barrier
        if (it + 1 < NT64) { stage(1 - buf); stage_x(1 - buf); }
        __syncthreads();

        // coalesced store of this tile; then prefetch tile it+2
        {
            long t0 = fwd ? (long)it * 64 : (long)(NT64 - 1 - it) * 64;
            #pragma unroll
            for (int j = 0; j < 2; j++) {
                int idx = tid + 512 * j;
                int t = idx >> 4, sg2 = idx & 15;
                const float* orow = ob + t * 65 + sg2 * 4;
                float4 v = make_float4(orow[0], orow[1], orow[2], orow[3]);
                *(float4*)(out + (bT + t0 + t) * Dn + z * 512 + h0 + sg2 * 4) = v;
            }
        }
        if (it + 2 < NT64) load_tile(it + 2);
    }

    // c_last: (B, 1, 2H) appended after out
    if (lane == 0) {
        float4 v = make_float4(carry[0], carry[1], carry[2], carry[3]);
        *(float4*)(out + (size_t)Bn * Tn * Dn + (size_t)b * 1024 + z * 512 + h0 + c0) = v;
    }
}

// ------------------------------- launch -------------------------------
#define SCAN_SMEM_TOTAL (2*3*64*66*2 + 2*64*65*4 + 2*64*66*2)   // sbuf + obuf + xsbuf = 100864

extern "C" void kernel_launch(void* const* d_in, const int* in_sizes, int n_in,
                              void* d_out, int out_size) {
    const float* x    = (const float*)d_in[0];
    const float* W    = (const float*)d_in[1];
    const float* bias = (const float*)d_in[2];
    float* out = (float*)d_out;
    (void)in_sizes; (void)n_in; (void)out_size;

    cudaFuncSetAttribute(sru_gemm, cudaFuncAttributeMaxDynamicSharedMemorySize, SMEM_TOTAL);
    cudaFuncSetAttribute(sru_scan, cudaFuncAttributeMaxDynamicSharedMemorySize, SCAN_SMEM_TOTAL);

    sru_xh  <<<(Mn * (Kn / 4)) / 256, 256>>>(x);
    sru_wt  <<<dim3(32, 32, 3), dim3(32, 8)>>>(W);
    sru_gemm<<<dim3(Nn / BN, Mn / BM), 256, SMEM_TOTAL>>>();
    sru_scan<<<256, 512, SCAN_SMEM_TOTAL>>>(bias, out);
}